// round 2
// baseline (speedup 1.0000x reference)
#include <cuda_runtime.h>
#include <math_constants.h>

// Per-block partials: [0..255] = sum of relu contributions, [256..511] = pos counts
__device__ float g_part[512];

__global__ __launch_bounds__(256) void triplet_main(const float* __restrict__ emb,
                                                    const int* __restrict__ labraw) {
    __shared__ float ei[128];       // anchor embedding
    __shared__ float norms[256];
    __shared__ float dneg[256];     // d[i,j] if j is "negative" (diff label OR j==i), else -inf
    __shared__ int   labsh[256];
    __shared__ int   s_is64;
    __shared__ float s_sum[256];
    __shared__ float s_cnt[256];

    const int i = blockIdx.x;
    const int t = threadIdx.x;

    // ---- label dtype detection (int64 vs int32; JAX may demote int64->int32) ----
    // Under int64, the high 32-bit word of every element (values in [0,16)) is 0.
    // Only the first 256 i32 words are touched here: in-bounds for both layouts.
    if (t == 0) s_is64 = 1;
    __syncthreads();
    if (t < 128) {
        if (labraw[2 * t + 1] != 0) s_is64 = 0;  // benign race: all writers store 0
    }
    __syncthreads();
    labsh[t] = s_is64 ? labraw[2 * t] : labraw[t];
    if (t < 128) ei[t] = emb[i * 128 + t];
    __syncthreads();

    // ---- phase 1: distance row d[i, t] ----
    const float* ej = emb + t * 128;
    float dot = 0.f, nj = 0.f;
    #pragma unroll
    for (int c = 0; c < 128; c += 4) {
        float4 v = *reinterpret_cast<const float4*>(ej + c);
        dot += v.x * ei[c] + v.y * ei[c + 1] + v.z * ei[c + 2] + v.w * ei[c + 3];
        nj  += v.x * v.x + v.y * v.y + v.z * v.z + v.w * v.w;
    }
    norms[t] = nj;
    __syncthreads();
    const float ni = norms[i];
    const float dk = sqrtf(fmaxf(ni + nj - 2.0f * dot, 1e-4f));

    const int li = labsh[i];
    const bool neg = (labsh[t] != li) || (t == i);   // (1 - pos) includes the diagonal
    dneg[t] = neg ? dk : -CUDART_INF_F;
    __syncthreads();

    // ---- phase 2: semi-hard negative scan for positive pairs (i, t) ----
    const bool ispos = (labsh[t] == li) && (t != i);
    float contrib = 0.f, cnt = 0.f;
    if (ispos) {
        cnt = 1.f;
        float maxNeg = -CUDART_INF_F;
        float minG   =  CUDART_INF_F;   // min over negatives with d[i,j] > d[i,k]
        #pragma unroll 8
        for (int j = 0; j < 256; j++) {
            float dj = dneg[j];                       // broadcast LDS
            maxNeg = fmaxf(maxNeg, dj);
            minG   = fminf(minG, dj > dk ? dj : CUDART_INF_F);
        }
        float v = (minG < CUDART_INF_F) ? (dk - minG)      // semi-hard exists
                                        : (dk - maxNeg);   // fallback: easiest negative
        contrib = fmaxf(v + 1.0f, 0.f);                    // relu(semi_hard + MARGIN)
    }

    // ---- block reduction ----
    s_sum[t] = contrib;
    s_cnt[t] = cnt;
    __syncthreads();
    #pragma unroll
    for (int s = 128; s > 0; s >>= 1) {
        if (t < s) { s_sum[t] += s_sum[t + s]; s_cnt[t] += s_cnt[t + s]; }
        __syncthreads();
    }
    if (t == 0) {
        g_part[i]       = s_sum[0];
        g_part[256 + i] = s_cnt[0];
    }
}

__global__ __launch_bounds__(256) void triplet_final(float* __restrict__ out) {
    __shared__ float s1[256];
    __shared__ float s2[256];
    const int t = threadIdx.x;
    s1[t] = g_part[t];
    s2[t] = g_part[256 + t];
    __syncthreads();
    #pragma unroll
    for (int s = 128; s > 0; s >>= 1) {
        if (t < s) { s1[t] += s1[t + s]; s2[t] += s2[t + s]; }
        __syncthreads();
    }
    if (t == 0) out[0] = s1[0] / s2[0];
}

extern "C" void kernel_launch(void* const* d_in, const int* in_sizes, int n_in,
                              void* d_out, int out_size) {
    const float* emb    = (const float*)d_in[0];   // [256, 128] float32
    const int*   labraw = (const int*)d_in[1];     // [256] int64 or int32 (detected in-kernel)
    float* out = (float*)d_out;

    triplet_main<<<256, 256>>>(emb, labraw);
    triplet_final<<<1, 256>>>(out);
}